// round 17
// baseline (speedup 1.0000x reference)
#include <cuda_runtime.h>
#include <stdint.h>

// NaiveVisCache, single kernel: face select + morton3d + int-table gather.
// d_in[0] = norm_ray_origins (B,3) f32, d_in[1] = viewdirs (B,3) f32,
// d_in[2] = cache (128^3,6) int32. Output: B f32 (0.0/1.0).
//
// Semantics (verified rel_err=0.0 across R6-R15): reference lowers v/inf_norm
// as v * fl_rn(1/inf_norm) -> __frcp_rn + __fmul_rn; where-chain falls back to
// face 0 when x*fl(1/x) rounds below 1.0.
//
// R16 = R15 staging + R13 occupancy, de-serialized:
//  - SEPARATE org/dir smem tiles -> all 6 coalesced LDG.128 (nL=4) issue
//    back-to-back (stream MLP=6), ONE __syncwarp total (R15 had 3 syncs and
//    serialized org->dir; R14 proved that serialization costs ~8us).
//  - __launch_bounds__(256,7) -> <=36 regs -> 87.5% occ ceiling (occ drives
//    achieved HBM BW: 90%->4.86, 63%->4.17, 53%->4.04 TB/s measured).
//  - __ldcs streams / __stcs store (traffic pinned ~167MB), 4 gathers/thread.

#define MIDPOINT 128

__device__ __forceinline__ unsigned expand_bits(unsigned v) {
    v = (v | (v << 16)) & 0x030000FFu;
    v = (v | (v << 8))  & 0x0300F00Fu;
    v = (v | (v << 4))  & 0x030C30C3u;
    v = (v | (v << 2))  & 0x09249249u;
    return v;
}

__global__ void __launch_bounds__(256, 7)
vis_cache_kernel(const float4* __restrict__ org4,
                 const float4* __restrict__ dir4,
                 const int*    __restrict__ cache,
                 float4*       __restrict__ out4,
                 int n_quads)  // n_rays / 4; n_quads % 32 == 0
{
    __shared__ float4 sorg[8][96];   // per-warp tiles: 32 quads * 3 float4
    __shared__ float4 sdir[8][96];

    int warp = threadIdx.x >> 5;
    int lane = threadIdx.x & 31;
    int warpQuadBase = (blockIdx.x * 8 + warp) * 32;
    int t = warpQuadBase + lane;
    if (warpQuadBase >= n_quads) return;   // whole-warp exit

    // ---- All 6 coalesced stream loads in flight at once (nL=4 each) ----
    {
        const float4* g1 = org4 + (size_t)warpQuadBase * 3;
        const float4* g2 = dir4 + (size_t)warpQuadBase * 3;
        float4 a0 = __ldcs(&g1[lane]);
        float4 a1 = __ldcs(&g1[lane + 32]);
        float4 a2 = __ldcs(&g1[lane + 64]);
        float4 b0 = __ldcs(&g2[lane]);
        float4 b1 = __ldcs(&g2[lane + 32]);
        float4 b2 = __ldcs(&g2[lane + 64]);
        sorg[warp][lane]      = a0;
        sorg[warp][lane + 32] = a1;
        sorg[warp][lane + 64] = a2;
        sdir[warp][lane]      = b0;
        sdir[warp][lane + 32] = b1;
        sdir[warp][lane + 64] = b2;
    }
    __syncwarp();

    float4 oa = sorg[warp][3 * lane + 0];
    float4 ob = sorg[warp][3 * lane + 1];
    float4 oc = sorg[warp][3 * lane + 2];
    float4 va = sdir[warp][3 * lane + 0];
    float4 vb = sdir[warp][3 * lane + 1];
    float4 vc = sdir[warp][3 * lane + 2];

    float of[12] = {oa.x, oa.y, oa.z, oa.w, ob.x, ob.y, ob.z, ob.w, oc.x, oc.y, oc.z, oc.w};
    float vf[12] = {va.x, va.y, va.z, va.w, vb.x, vb.y, vb.z, vb.w, vc.x, vc.y, vc.z, vc.w};

    // Phase 1: morton base indices (exact-integer path).
    unsigned entry[4];
    #pragma unroll
    for (int j = 0; j < 4; j++) {
        float cx = fminf(fmaxf((of[3 * j + 0] * 0.5f + 0.5f) * 128.0f, 0.0f), 127.0f);
        float cy = fminf(fmaxf((of[3 * j + 1] * 0.5f + 0.5f) * 128.0f, 0.0f), 127.0f);
        float cz = fminf(fmaxf((of[3 * j + 2] * 0.5f + 0.5f) * 128.0f, 0.0f), 127.0f);

        unsigned idx = expand_bits((unsigned)(int)cx)
                     | (expand_bits((unsigned)(int)cy) << 1)
                     | (expand_bits((unsigned)(int)cz) << 2);
        entry[j] = idx * 6u;
    }

    // Phase 2: face select (reciprocal-multiply, bit-matching the reference).
    #pragma unroll
    for (int j = 0; j < 4; j++) {
        float a = vf[3 * j + 0];
        float b = vf[3 * j + 1];
        float c = vf[3 * j + 2];

        float n = fmaxf(fabsf(a), fmaxf(fabsf(b), fabsf(c)));
        float r  = __frcp_rn(n);
        float sa = __fmul_rn(a, r);
        float sb = __fmul_rn(b, r);
        float sc = __fmul_rn(c, r);

        int face = 0;
        if (sa >=  1.0f) face = 0;
        if (sa <= -1.0f) face = 1;
        if (sb >=  1.0f) face = 2;
        if (sb <= -1.0f) face = 3;
        if (sc >=  1.0f) face = 4;
        if (sc <= -1.0f) face = 5;

        entry[j] += (unsigned)face;
    }

    // Phase 3: 4 independent gathers in flight (default policy: table owns L2).
    int v0 = __ldg(&cache[entry[0]]);
    int v1 = __ldg(&cache[entry[1]]);
    int v2 = __ldg(&cache[entry[2]]);
    int v3 = __ldg(&cache[entry[3]]);

    float4 res = make_float4(v0 > MIDPOINT ? 1.0f : 0.0f,
                             v1 > MIDPOINT ? 1.0f : 0.0f,
                             v2 > MIDPOINT ? 1.0f : 0.0f,
                             v3 > MIDPOINT ? 1.0f : 0.0f);

    __stcs(&out4[t], res);   // coalesced, never re-read
}

extern "C" void kernel_launch(void* const* d_in, const int* in_sizes, int n_in,
                              void* d_out, int out_size)
{
    const float4* org4  = (const float4*)d_in[0];
    const float4* dir4  = (const float4*)d_in[1];
    const int*    cache = (const int*)d_in[2];
    float4*       out4  = (float4*)d_out;

    int n_rays  = in_sizes[0] / 3;   // 4194304
    int n_quads = n_rays / 4;        // 1048576 (divisible by 32)

    vis_cache_kernel<<<(n_quads + 255) / 256, 256>>>(org4, dir4, cache, out4, n_quads);
}